// round 3
// baseline (speedup 1.0000x reference)
#include <cuda_runtime.h>
#include <math.h>

// Problem constants
#define NT 256           // threads per block
#define GMAX 64          // number of ground-truth boxes

// iou > 0.8  <=>  inter > (0.8/1.8)*(ar+ag)
// iou < 0.3  <=>  inter < (0.3/1.3)*(ar+ag)
#define SPOS (0.8f / 1.8f)
#define SNEG (0.3f / 1.3f)

// Global accumulators. Zero-initialized at module load; the finalize step
// (run by the last-finishing block) re-zeroes them, so every kernel_launch
// (correctness run and every graph replay) starts from the zeroed state.
// Key encoding: (iou_bits << 32) | (0xFFFFFFFF - r). key==0 <=> no pair with
// inter>0 anywhere => argmax index 0 (matches jnp.argmax on all-equal row).
__device__ unsigned long long g_key[GMAX];   // zero-init
__device__ int          g_posc;
__device__ int          g_negc;
__device__ int          g_cnt;
__device__ float        g_psum;
__device__ float        g_rsum;
__device__ unsigned int g_ticket;

__device__ __forceinline__ float sl1(float d) {
    return (d < 1.0f) ? 0.5f * d * d : d - 0.5f;
}

// ---------------------------------------------------------------------------
// Fused kernel: per-region labels + per-gt argmax + smooth-L1 partials,
// block-level merge to global atomics, and the LAST block (ticket) runs the
// scatter fixups + final loss, then resets the globals for the next replay.
// ---------------------------------------------------------------------------
__global__ __launch_bounds__(NT)
void rpn_fused(const float* __restrict__ scores,
               const float4* __restrict__ regions,
               const float4* __restrict__ anchors,
               const float4* __restrict__ gts,
               int R, int NB,
               float* __restrict__ out, int out_size)
{
    __shared__ float4 s_gt[GMAX];
    // s_aux[g] = (ag, SPOS*ag, SNEG*ag, curA)   curA ~ iou/(1+iou) of running max
    __shared__ float4 s_aux[GMAX];
    __shared__ unsigned long long s_key[GMAX];
    __shared__ int    s_cnt;
    __shared__ float  s_psum, s_rsum;
    __shared__ int    s_last;
    // finalize-only shared state
    __shared__ int    s_best[GMAX];
    __shared__ int    s_padd, s_nsub, s_cadd;
    __shared__ float  s_psadd, s_radd;

    const int tid = threadIdx.x;
    if (tid < GMAX) {
        float4 b = gts[tid];
        s_gt[tid] = b;
        const float ag = (b.z - b.x) * (b.w - b.y);
        s_aux[tid] = make_float4(ag, SPOS * ag, SNEG * ag, 0.0f);
        s_key[tid] = 0ull;
    }
    if (tid == 0) { s_cnt = 0; s_psum = 0.f; s_rsum = 0.f; }
    __syncthreads();

    const int r = blockIdx.x * NT + tid;
    bool hasPos = false;
    bool allNeg = true;
    float4 rb = make_float4(0.f, 0.f, 0.f, 0.f);
    float  ar = 0.f;

    if (r < R) {
        rb = regions[r];
        ar = (rb.z - rb.x) * (rb.w - rb.y);
        const float rpos = SPOS * ar;
        const float rneg = SNEG * ar;

        #pragma unroll 16
        for (int g = 0; g < GMAX; ++g) {
            const float4 gb = s_gt[g];
            const float4 ax = s_aux[g];
            const float dx = fmaxf(fminf(rb.z, gb.z) - fmaxf(rb.x, gb.x), 0.0f);
            const float dy = fmaxf(fminf(rb.w, gb.w) - fmaxf(rb.y, gb.y), 0.0f);
            const float inter = dx * dy;

            hasPos = hasPos || (inter > rpos + ax.y);
            allNeg = allNeg && (inter < rneg + ax.z);

            // argmax filter: iou > cur  <=>  inter/(sum-inter) > curA/(1-curA)
            //            <=>  inter > curA * sum   (curA = curIoU/(1+curIoU))
            // curA stored slightly lowered so ties/borderline still enter the
            // atomicMax (which tie-breaks on index correctly).
            const float sum = ar + ax.x;
            if (inter > ax.w * sum) {
                const float iou = inter / (sum - inter);
                const unsigned long long key =
                    ((unsigned long long)__float_as_uint(iou) << 32) |
                    (unsigned long long)(0xFFFFFFFFu - (unsigned)r);
                const unsigned long long old = atomicMax(&s_key[g], key);
                if (old < key)
                    s_aux[g].w = (inter / sum) * 0.999999f;
            }
        }
    }

    const int posc = __syncthreads_count(hasPos);
    const int negc = __syncthreads_count(allNeg);

    if (hasPos) {
        atomicAdd(&s_psum, scores[r]);

        // regression pairs with iou > 0.8 (anchors cancel except aw, ah)
        const float4 ab  = anchors[r];
        const float  aw  = ab.z - ab.x;
        const float  ah  = ab.w - ab.y;
        const float  rcx = (rb.x + rb.z) * 0.5f;
        const float  rcy = (rb.y + rb.w) * 0.5f;
        const float  lrw = logf(rb.z - rb.x);
        const float  lrh = logf(rb.w - rb.y);
        const float  rpos = SPOS * ar;

        float rsum = 0.0f;
        int   c    = 0;
        for (int g = 0; g < GMAX; ++g) {
            const float4 gb = s_gt[g];
            const float4 ax = s_aux[g];
            const float dx = fmaxf(fminf(rb.z, gb.z) - fmaxf(rb.x, gb.x), 0.0f);
            const float dy = fmaxf(fminf(rb.w, gb.w) - fmaxf(rb.y, gb.y), 0.0f);
            const float inter = dx * dy;
            if (inter > rpos + ax.y) {
                const float gcx = (gb.x + gb.z) * 0.5f;
                const float gcy = (gb.y + gb.w) * 0.5f;
                const float d0 = fabsf(rcx - gcx) / aw;
                const float d1 = fabsf(rcy - gcy) / ah;
                const float d2 = fabsf(lrw - logf(gb.z - gb.x));
                const float d3 = fabsf(lrh - logf(gb.w - gb.y));
                rsum += 0.25f * (sl1(d0) + sl1(d1) + sl1(d2) + sl1(d3));
                ++c;
            }
        }
        if (c) { atomicAdd(&s_rsum, rsum); atomicAdd(&s_cnt, c); }
    }
    __syncthreads();

    // Block-end merge straight into global accumulators.
    if (tid < GMAX) {
        const unsigned long long k = s_key[tid];
        if (k) atomicMax(&g_key[tid], k);
    }
    if (tid == 0) {
        if (posc)  { atomicAdd(&g_posc, posc); atomicAdd(&g_psum, s_psum); }
        if (negc)    atomicAdd(&g_negc, negc);
        if (s_cnt) { atomicAdd(&g_cnt, s_cnt); atomicAdd(&g_rsum, s_rsum); }
    }
    __threadfence();        // order this block's merges before the ticket
    __syncthreads();
    if (tid == 0) {
        s_last = (atomicAdd(&g_ticket, 1u) == (unsigned)(NB - 1));
        s_padd = 0; s_nsub = 0; s_cadd = 0; s_psadd = 0.f; s_radd = 0.f;
    }
    __syncthreads();
    if (!s_last) return;

    // ======================= FINALIZE (last block only) =====================
    __threadfence();        // acquire: all other blocks' merges are visible

    if (tid < GMAX) {
        const unsigned long long k = *(volatile unsigned long long*)&g_key[tid];
        s_best[tid] = (k == 0ull) ? 0
                    : (int)(0xFFFFFFFFu - (unsigned)(k & 0xFFFFFFFFull));
    }
    __syncthreads();

    if (tid < GMAX) {
        const int g = tid;
        const int rr = s_best[g];

        bool owner = true;                      // first gt that uses this row
        for (int j = 0; j < g; ++j)
            if (s_best[j] == rr) owner = false;

        const float4 rbb = regions[rr];
        const float  arr = (rbb.z - rbb.x) * (rbb.w - rbb.y);
        const float  rposF = SPOS * arr;
        const float  rnegF = SNEG * arr;

        bool hP = false, aN = true;
        float inter_g = 0.f, pos_g = 0.f;
        for (int j = 0; j < GMAX; ++j) {
            const float4 gb = s_gt[j];
            const float4 ax = s_aux[j];
            const float dx = fmaxf(fminf(rbb.z, gb.z) - fmaxf(rbb.x, gb.x), 0.0f);
            const float dy = fmaxf(fminf(rbb.w, gb.w) - fmaxf(rbb.y, gb.y), 0.0f);
            const float inter = dx * dy;
            hP = hP || (inter > rposF + ax.y);
            aN = aN && (inter < rnegF + ax.z);
            if (j == g) { inter_g = inter; pos_g = rposF + ax.y; }
        }

        if (owner) {
            if (!hP) {                          // row becomes pos via scatter
                atomicAdd(&s_padd, 1);
                atomicAdd(&s_psadd, scores[rr]);
            }
            if (aN) atomicAdd(&s_nsub, 1);     // was counted neg in pass 1
        }

        // scatter pair not already counted as an iou>0.8 pair
        if (!(inter_g > pos_g)) {
            const float4 ab  = anchors[rr];
            const float  aw  = ab.z - ab.x;
            const float  ah  = ab.w - ab.y;
            const float4 gb  = s_gt[g];
            const float  rcx = (rbb.x + rbb.z) * 0.5f;
            const float  rcy = (rbb.y + rbb.w) * 0.5f;
            const float  gcx = (gb.x + gb.z) * 0.5f;
            const float  gcy = (gb.y + gb.w) * 0.5f;
            const float  d0  = fabsf(rcx - gcx) / aw;
            const float  d1  = fabsf(rcy - gcy) / ah;
            const float  d2  = fabsf(logf(rbb.z - rbb.x) - logf(gb.z - gb.x));
            const float  d3  = fabsf(logf(rbb.w - rbb.y) - logf(gb.w - gb.y));
            atomicAdd(&s_radd, 0.25f * (sl1(d0) + sl1(d1) + sl1(d2) + sl1(d3)));
            atomicAdd(&s_cadd, 1);
        }
    }
    __syncthreads();

    if (tid == 0) {
        const int posG = *(volatile int*)&g_posc;
        const int negG = *(volatile int*)&g_negc;
        const int cntG = *(volatile int*)&g_cnt;
        const float psG = *(volatile float*)&g_psum;
        const float rsG = *(volatile float*)&g_rsum;

        const double n_pos = (double)(posG + s_padd);
        const double n_neg = (double)(negG - s_nsub);
        const double n     = n_pos + n_neg;

        const double C1  = 0.3132616875182228;   // log1p(exp(-1))
        const double LN2 = 0.6931471805599453;

        const double fpos_sum = n_pos * (1.0 + C1) - (double)(psG + s_psadd);
        const double cls      = (fpos_sum + n_neg * LN2) / n;

        const double reg = (double)(rsG + s_radd);
        const double cnt = (double)(cntG + s_cadd);

        const double loss = cls / n + 10.0 * reg / cnt;

        out[0] = (float)loss;
        if (out_size > 1) out[1] = (float)s_best[GMAX - 1];  // max_iou_idx
    }

    // Reset globals for the next call (all reads above are done).
    __syncthreads();
    if (tid < GMAX) g_key[tid] = 0ull;
    if (tid == 0) {
        g_posc = 0; g_negc = 0; g_cnt = 0;
        g_psum = 0.f; g_rsum = 0.f;
        g_ticket = 0u;
    }
}

// ---------------------------------------------------------------------------
// Launch
// ---------------------------------------------------------------------------
extern "C" void kernel_launch(void* const* d_in, const int* in_sizes, int n_in,
                              void* d_out, int out_size)
{
    const float*  scores  = (const float*) d_in[0];
    const float4* regions = (const float4*)d_in[1];
    const float4* anchors = (const float4*)d_in[2];
    const float4* gts     = (const float4*)d_in[3];
    const int R  = in_sizes[0];
    const int NB = (R + NT - 1) / NT;

    rpn_fused<<<NB, NT>>>(scores, regions, anchors, gts, R, NB,
                          (float*)d_out, out_size);
}

// round 4
// speedup vs baseline: 1.0120x; 1.0120x over previous
#include <cuda_runtime.h>
#include <math.h>

#define NT 256           // threads per block (8 warps)
#define GMAX 64          // number of ground-truth boxes

// iou > 0.8  <=>  inter > (0.8/1.8)*(ar+ag) ; iou < 0.3 <=> inter < (0.3/1.3)*(ar+ag)
#define SPOS (0.8f / 1.8f)
#define SNEG (0.3f / 1.3f)

// Global accumulators. Zero-initialized at module load; the finalize step
// (last-ticket block) re-zeroes them, so every kernel_launch / graph replay
// starts from the zeroed state.
// Key encoding: (iou_bits << 32) | (0xFFFFFFFF - r). key==0 <=> no pair with
// inter>0 => argmax index 0 (matches jnp.argmax on an all-equal row).
__device__ unsigned long long g_key[GMAX];
__device__ int          g_posc;
__device__ int          g_negc;
__device__ int          g_cnt;
__device__ float        g_psum;
__device__ float        g_rsum;
__device__ unsigned int g_ticket;

__device__ __forceinline__ float sl1(float d) {
    return (d < 1.0f) ? 0.5f * d * d : d - 0.5f;
}

__device__ __forceinline__ unsigned long long pack_key(float iou, int r) {
    return ((unsigned long long)__float_as_uint(iou) << 32) |
           (unsigned long long)(0xFFFFFFFFu - (unsigned)r);
}

// ---------------------------------------------------------------------------
// Fused kernel, register-resident inner loop.
// Lane L of every warp owns gts L and L+32 in registers. Each warp processes
// 32 regions; the region box is a uniform (broadcast) load. Argmax state is
// per-lane registers; labels via warp votes. Block-end merges via one shared
// pass + global REDs. Last block (ticket) finalizes the loss.
// ---------------------------------------------------------------------------
__global__ __launch_bounds__(NT)
void rpn_fused(const float* __restrict__ scores,
               const float4* __restrict__ regions,
               const float4* __restrict__ anchors,
               const float4* __restrict__ gts,
               int R, int NB,
               float* __restrict__ out, int out_size)
{
    __shared__ unsigned long long s_key[GMAX];
    __shared__ int    s_posc, s_negc, s_cnt;
    __shared__ float  s_psum, s_rsum;
    __shared__ int    s_last;
    // finalize-only
    __shared__ float4 f_gt[GMAX];
    __shared__ float  f_ag[GMAX];
    __shared__ int    f_best[GMAX];
    __shared__ int    f_padd, f_nsub, f_cadd;
    __shared__ float  f_psadd, f_radd;

    const int tid  = threadIdx.x;
    const int lane = tid & 31;
    const int wid  = tid >> 5;

    if (tid < GMAX) s_key[tid] = 0ull;
    if (tid == 0) { s_posc = 0; s_negc = 0; s_cnt = 0; s_psum = 0.f; s_rsum = 0.f; }

    // Two gts per lane, fully in registers.
    const float4 gA = gts[lane];
    const float4 gB = gts[lane + 32];
    const float agA = (gA.z - gA.x) * (gA.w - gA.y);
    const float agB = (gB.z - gB.x) * (gB.w - gB.y);
    const float posA = SPOS * agA, negA = SNEG * agA;
    const float posB = SPOS * agB, negB = SNEG * agB;

    // Per-lane running argmax (IEEE-rounded iou, strict >, increasing r order
    // => first max kept, matching jnp.argmax).
    float bestIouA = 0.f, bestIouB = 0.f;
    float bestFA   = 0.f, bestFB   = 0.f;   // bestIou * (1 - 2ulp) filter value
    int   bestIdxA = 0,   bestIdxB = 0;

    int   posc = 0, negc = 0;
    float psum = 0.f;          // lane 0 only
    float rsum = 0.f; int rcnt = 0;

    const int base = blockIdx.x * NT + wid * 32;
    __syncthreads();

    #pragma unroll 4
    for (int j = 0; j < 32; ++j) {
        const int r = base + j;
        bool pA = false, pB = false, nA = true, nB = true;
        if (r < R) {
            const float4 rb = regions[r];        // uniform across warp (broadcast)
            const float ar   = (rb.z - rb.x) * (rb.w - rb.y);
            const float rpos = SPOS * ar;
            const float rneg = SNEG * ar;

            // ---- gt A ----
            const float dxA = fmaxf(fminf(rb.z, gA.z) - fmaxf(rb.x, gA.x), 0.f);
            const float dyA = fmaxf(fminf(rb.w, gA.w) - fmaxf(rb.y, gA.y), 0.f);
            const float iA  = dxA * dyA;
            pA = iA > rpos + posA;
            nA = iA < rneg + negA;
            {
                const float denom = (ar + agA) - iA;
                if (iA > bestFA * denom) {           // rare after warm-up
                    const float iou = iA / denom;    // IEEE-rounded, matches ref
                    if (iou > bestIouA) {
                        bestIouA = iou; bestIdxA = r;
                        bestFA = iou * 0.99999988f;  // loosened filter (ties pass)
                    }
                }
            }
            // ---- gt B ----
            const float dxB = fmaxf(fminf(rb.z, gB.z) - fmaxf(rb.x, gB.x), 0.f);
            const float dyB = fmaxf(fminf(rb.w, gB.w) - fmaxf(rb.y, gB.y), 0.f);
            const float iB  = dxB * dyB;
            pB = iB > rpos + posB;
            nB = iB < rneg + negB;
            {
                const float denom = (ar + agB) - iB;
                if (iB > bestFB * denom) {
                    const float iou = iB / denom;
                    if (iou > bestIouB) {
                        bestIouB = iou; bestIdxB = r;
                        bestFB = iou * 0.99999988f;
                    }
                }
            }

            // ---- rare regression pairs (iou > 0.8) ----
            if (pA | pB) {
                const float4 ab = anchors[r];
                const float aw  = ab.z - ab.x;
                const float ah  = ab.w - ab.y;
                const float rcx = (rb.x + rb.z) * 0.5f;
                const float rcy = (rb.y + rb.w) * 0.5f;
                const float lrw = logf(rb.z - rb.x);
                const float lrh = logf(rb.w - rb.y);
                if (pA) {
                    const float d0 = fabsf(rcx - (gA.x + gA.z) * 0.5f) / aw;
                    const float d1 = fabsf(rcy - (gA.y + gA.w) * 0.5f) / ah;
                    const float d2 = fabsf(lrw - logf(gA.z - gA.x));
                    const float d3 = fabsf(lrh - logf(gA.w - gA.y));
                    rsum += 0.25f * (sl1(d0) + sl1(d1) + sl1(d2) + sl1(d3));
                    ++rcnt;
                }
                if (pB) {
                    const float d0 = fabsf(rcx - (gB.x + gB.z) * 0.5f) / aw;
                    const float d1 = fabsf(rcy - (gB.y + gB.w) * 0.5f) / ah;
                    const float d2 = fabsf(lrw - logf(gB.z - gB.x));
                    const float d3 = fabsf(lrh - logf(gB.w - gB.y));
                    rsum += 0.25f * (sl1(d0) + sl1(d1) + sl1(d2) + sl1(d3));
                    ++rcnt;
                }
            }
        }
        // ---- warp-wide labels for region r ----
        const bool anyPos = __any_sync(0xFFFFFFFFu, pA || pB);
        const bool allNeg = __all_sync(0xFFFFFFFFu, nA && nB);
        if (lane == 0 && r < R) {
            posc += anyPos;
            negc += allNeg;
            if (anyPos) psum += scores[r];
        }
    }

    // ---- block-level merge ----
    if (bestIouA > 0.f) atomicMax(&s_key[lane],      pack_key(bestIouA, bestIdxA));
    if (bestIouB > 0.f) atomicMax(&s_key[lane + 32], pack_key(bestIouB, bestIdxB));
    if (lane == 0) {
        if (posc) { atomicAdd(&s_posc, posc); atomicAdd(&s_psum, psum); }
        if (negc)   atomicAdd(&s_negc, negc);
    }
    if (__any_sync(0xFFFFFFFFu, rcnt)) {
        #pragma unroll
        for (int o = 16; o > 0; o >>= 1) {
            rsum += __shfl_xor_sync(0xFFFFFFFFu, rsum, o);
            rcnt += __shfl_xor_sync(0xFFFFFFFFu, rcnt, o);
        }
        if (lane == 0 && rcnt) { atomicAdd(&s_rsum, rsum); atomicAdd(&s_cnt, rcnt); }
    }
    __syncthreads();

    if (tid < GMAX) {
        const unsigned long long k = s_key[tid];
        if (k) atomicMax(&g_key[tid], k);
    }
    if (tid == 0) {
        if (s_posc) { atomicAdd(&g_posc, s_posc); atomicAdd(&g_psum, s_psum); }
        if (s_negc)   atomicAdd(&g_negc, s_negc);
        if (s_cnt)  { atomicAdd(&g_cnt, s_cnt);   atomicAdd(&g_rsum, s_rsum); }
    }
    __threadfence();
    __syncthreads();
    if (tid == 0) {
        s_last = (atomicAdd(&g_ticket, 1u) == (unsigned)(NB - 1));
        f_padd = 0; f_nsub = 0; f_cadd = 0; f_psadd = 0.f; f_radd = 0.f;
    }
    __syncthreads();
    if (!s_last) return;

    // ======================= FINALIZE (last block only) =====================
    __threadfence();   // acquire all other blocks' merges

    if (tid < GMAX) {
        float4 b = gts[tid];
        f_gt[tid] = b;
        f_ag[tid] = (b.z - b.x) * (b.w - b.y);
        const unsigned long long k = *(volatile unsigned long long*)&g_key[tid];
        f_best[tid] = (k == 0ull) ? 0
                    : (int)(0xFFFFFFFFu - (unsigned)(k & 0xFFFFFFFFull));
    }
    __syncthreads();

    if (tid < GMAX) {
        const int g  = tid;
        const int rr = f_best[g];

        bool owner = true;                       // first gt using this row
        for (int j = 0; j < g; ++j)
            if (f_best[j] == rr) owner = false;

        const float4 rbb  = regions[rr];
        const float  arr  = (rbb.z - rbb.x) * (rbb.w - rbb.y);
        const float  rposF = SPOS * arr;
        const float  rnegF = SNEG * arr;

        bool hP = false, aN = true;
        float inter_g = 0.f, pos_g = 0.f;
        for (int j = 0; j < GMAX; ++j) {
            const float4 gb = f_gt[j];
            const float dx = fmaxf(fminf(rbb.z, gb.z) - fmaxf(rbb.x, gb.x), 0.f);
            const float dy = fmaxf(fminf(rbb.w, gb.w) - fmaxf(rbb.y, gb.y), 0.f);
            const float inter = dx * dy;
            const float pth = rposF + SPOS * f_ag[j];
            hP = hP || (inter > pth);
            aN = aN && (inter < rnegF + SNEG * f_ag[j]);
            if (j == g) { inter_g = inter; pos_g = pth; }
        }

        if (owner) {
            if (!hP) {                           // row becomes pos via scatter
                atomicAdd(&f_padd, 1);
                atomicAdd(&f_psadd, scores[rr]);
            }
            if (aN) atomicAdd(&f_nsub, 1);       // was counted neg in main pass
        }

        // scatter pair not already counted as an iou>0.8 pair
        if (!(inter_g > pos_g)) {
            const float4 ab  = anchors[rr];
            const float  aw  = ab.z - ab.x;
            const float  ah  = ab.w - ab.y;
            const float4 gb  = f_gt[g];
            const float  rcx = (rbb.x + rbb.z) * 0.5f;
            const float  rcy = (rbb.y + rbb.w) * 0.5f;
            const float  d0  = fabsf(rcx - (gb.x + gb.z) * 0.5f) / aw;
            const float  d1  = fabsf(rcy - (gb.y + gb.w) * 0.5f) / ah;
            const float  d2  = fabsf(logf(rbb.z - rbb.x) - logf(gb.z - gb.x));
            const float  d3  = fabsf(logf(rbb.w - rbb.y) - logf(gb.w - gb.y));
            atomicAdd(&f_radd, 0.25f * (sl1(d0) + sl1(d1) + sl1(d2) + sl1(d3)));
            atomicAdd(&f_cadd, 1);
        }
    }
    __syncthreads();

    if (tid == 0) {
        const int   posG = *(volatile int*)&g_posc;
        const int   negG = *(volatile int*)&g_negc;
        const int   cntG = *(volatile int*)&g_cnt;
        const float psG  = *(volatile float*)&g_psum;
        const float rsG  = *(volatile float*)&g_rsum;

        const double n_pos = (double)(posG + f_padd);
        const double n_neg = (double)(negG - f_nsub);
        const double n     = n_pos + n_neg;

        const double C1  = 0.3132616875182228;   // log1p(exp(-1))
        const double LN2 = 0.6931471805599453;

        const double fpos_sum = n_pos * (1.0 + C1) - (double)(psG + f_psadd);
        const double cls      = (fpos_sum + n_neg * LN2) / n;

        const double reg = (double)(rsG + f_radd);
        const double cnt = (double)(cntG + f_cadd);

        const double loss = cls / n + 10.0 * reg / cnt;

        out[0] = (float)loss;
        if (out_size > 1) out[1] = (float)f_best[GMAX - 1];  // max_iou_idx
    }

    // Reset globals for the next call / replay.
    __syncthreads();
    if (tid < GMAX) g_key[tid] = 0ull;
    if (tid == 0) {
        g_posc = 0; g_negc = 0; g_cnt = 0;
        g_psum = 0.f; g_rsum = 0.f;
        g_ticket = 0u;
    }
}

// ---------------------------------------------------------------------------
// Launch
// ---------------------------------------------------------------------------
extern "C" void kernel_launch(void* const* d_in, const int* in_sizes, int n_in,
                              void* d_out, int out_size)
{
    const float*  scores  = (const float*) d_in[0];
    const float4* regions = (const float4*)d_in[1];
    const float4* anchors = (const float4*)d_in[2];
    const float4* gts     = (const float4*)d_in[3];
    const int R  = in_sizes[0];
    const int NB = (R + NT - 1) / NT;

    rpn_fused<<<NB, NT>>>(scores, regions, anchors, gts, R, NB,
                          (float*)d_out, out_size);
}

// round 5
// speedup vs baseline: 1.1224x; 1.1092x over previous
#include <cuda_runtime.h>
#include <math.h>

// Problem constants
#define NT 256           // threads per block
#define GMAX 64          // number of ground-truth boxes

// iou > 0.8  <=>  inter > (0.8/1.8)*(ar+ag)
// iou < 0.3  <=>  inter < (0.3/1.3)*(ar+ag)
#define SPOS (0.8f / 1.8f)
#define SNEG (0.3f / 1.3f)

// Global accumulators. Zero-initialized at module load; the finalize step
// (last-ticket block) re-zeroes them, so every kernel_launch / graph replay
// starts from the zeroed state.
// Key encoding: (iou_bits << 32) | (0xFFFFFFFF - r). key==0 <=> no pair with
// inter>0 anywhere => argmax index 0 (matches jnp.argmax on all-equal row).
__device__ unsigned long long g_key[GMAX];
__device__ int          g_posc;
__device__ int          g_negc;
__device__ int          g_cnt;
__device__ float        g_psum;
__device__ float        g_rsum;
__device__ unsigned int g_ticket;

__device__ __forceinline__ float sl1(float d) {
    return (d < 1.0f) ? 0.5f * d * d : d - 0.5f;
}

// ---------------------------------------------------------------------------
// Fused kernel. Main pass is the round-2 pass1 loop (fastest measured):
// one thread per region, gts in read-only shared, per-gt argmax via shared
// packed key + division-free filter + rare atomicMax. Block-end merge goes to
// global atomics; the LAST block (ticket) runs the scatter fixups + final
// loss in-kernel, then resets globals for the next replay.
// ---------------------------------------------------------------------------
__global__ __launch_bounds__(NT)
void rpn_fused(const float* __restrict__ scores,
               const float4* __restrict__ regions,
               const float4* __restrict__ anchors,
               const float4* __restrict__ gts,
               int R, int NB,
               float* __restrict__ out, int out_size)
{
    __shared__ float4 s_gt[GMAX];
    __shared__ float  s_ag[GMAX];
    __shared__ unsigned long long s_key[GMAX];
    __shared__ int   s_posc, s_negc, s_cnt;
    __shared__ float s_psum, s_rsum;
    __shared__ int   s_last;
    // finalize-only
    __shared__ int   f_best[GMAX];
    __shared__ int   f_padd, f_nsub, f_cadd;
    __shared__ float f_psadd, f_radd;

    const int tid = threadIdx.x;
    if (tid < GMAX) {
        float4 b = gts[tid];
        s_gt[tid] = b;
        s_ag[tid] = (b.z - b.x) * (b.w - b.y);
        s_key[tid] = 0ull;
    }
    if (tid == 0) { s_posc = 0; s_negc = 0; s_cnt = 0; s_psum = 0.f; s_rsum = 0.f; }
    __syncthreads();

    const int r = blockIdx.x * NT + tid;
    if (r < R) {
        const float4 rb = regions[r];
        const float  ar = (rb.z - rb.x) * (rb.w - rb.y);

        bool hasPos = false;
        bool allNeg = true;

        #pragma unroll 16
        for (int g = 0; g < GMAX; ++g) {
            const float4 gb = s_gt[g];
            float dx = fminf(rb.z, gb.z) - fmaxf(rb.x, gb.x);
            float dy = fminf(rb.w, gb.w) - fmaxf(rb.y, gb.y);
            dx = fmaxf(dx, 0.0f);
            dy = fmaxf(dy, 0.0f);
            const float inter = dx * dy;
            const float sum   = ar + s_ag[g];

            hasPos = hasPos || (inter > SPOS * sum);
            allNeg = allNeg && (inter < SNEG * sum);

            // argmax filter without division: iou > cur  <=>  inter > cur*denom
            const float denom = sum - inter;   // always > 0
            const unsigned long long curk =
                *(volatile unsigned long long*)&s_key[g];
            const float cur = __uint_as_float((unsigned)(curk >> 32));
            if (inter > cur * denom) {
                const float iou = inter / denom;
                const unsigned long long key =
                    ((unsigned long long)__float_as_uint(iou) << 32) |
                    (unsigned long long)(0xFFFFFFFFu - (unsigned)r);
                atomicMax(&s_key[g], key);
            }
        }

        if (allNeg) atomicAdd(&s_negc, 1);
        if (hasPos) {
            atomicAdd(&s_posc, 1);
            atomicAdd(&s_psum, scores[r]);

            // regression pairs with iou > 0.8 (anchors cancel except aw, ah)
            const float4 ab  = anchors[r];
            const float  aw  = ab.z - ab.x;
            const float  ah  = ab.w - ab.y;
            const float  rcx = (rb.x + rb.z) * 0.5f;
            const float  rcy = (rb.y + rb.w) * 0.5f;
            const float  lrw = logf(rb.z - rb.x);
            const float  lrh = logf(rb.w - rb.y);

            float rsum = 0.0f;
            int   c    = 0;
            for (int g = 0; g < GMAX; ++g) {
                const float4 gb = s_gt[g];
                float dx = fminf(rb.z, gb.z) - fmaxf(rb.x, gb.x);
                float dy = fminf(rb.w, gb.w) - fmaxf(rb.y, gb.y);
                dx = fmaxf(dx, 0.0f);
                dy = fmaxf(dy, 0.0f);
                const float inter = dx * dy;
                const float sum   = ar + s_ag[g];
                if (inter > SPOS * sum) {
                    const float gcx = (gb.x + gb.z) * 0.5f;
                    const float gcy = (gb.y + gb.w) * 0.5f;
                    const float d0 = fabsf(rcx - gcx) / aw;
                    const float d1 = fabsf(rcy - gcy) / ah;
                    const float d2 = fabsf(lrw - logf(gb.z - gb.x));
                    const float d3 = fabsf(lrh - logf(gb.w - gb.y));
                    rsum += 0.25f * (sl1(d0) + sl1(d1) + sl1(d2) + sl1(d3));
                    ++c;
                }
            }
            if (c) { atomicAdd(&s_rsum, rsum); atomicAdd(&s_cnt, c); }
        }
    }

    __syncthreads();
    // Block-end merge straight into global accumulators (no-return -> RED).
    if (tid < GMAX) {
        const unsigned long long k = s_key[tid];
        if (k) atomicMax(&g_key[tid], k);
    }
    if (tid == 0) {
        if (s_posc) { atomicAdd(&g_posc, s_posc); atomicAdd(&g_psum, s_psum); }
        if (s_negc)   atomicAdd(&g_negc, s_negc);
        if (s_cnt)  { atomicAdd(&g_cnt, s_cnt);   atomicAdd(&g_rsum, s_rsum); }
    }
    __threadfence();        // order this block's merges before the ticket
    __syncthreads();
    if (tid == 0) {
        s_last = (atomicAdd(&g_ticket, 1u) == (unsigned)(NB - 1));
        f_padd = 0; f_nsub = 0; f_cadd = 0; f_psadd = 0.f; f_radd = 0.f;
    }
    __syncthreads();
    if (!s_last) return;

    // ======================= FINALIZE (last block only) =====================
    __threadfence();        // acquire: all other blocks' merges are visible

    if (tid < GMAX) {
        const unsigned long long k = *(volatile unsigned long long*)&g_key[tid];
        f_best[tid] = (k == 0ull) ? 0
                    : (int)(0xFFFFFFFFu - (unsigned)(k & 0xFFFFFFFFull));
    }
    __syncthreads();

    if (tid < GMAX) {
        const int g  = tid;
        const int rr = f_best[g];

        bool owner = true;                       // first gt using this row
        for (int j = 0; j < g; ++j)
            if (f_best[j] == rr) owner = false;

        const float4 rbb  = regions[rr];
        const float  arr  = (rbb.z - rbb.x) * (rbb.w - rbb.y);

        bool hP = false, aN = true;
        float inter_g = 0.f, pos_g = 0.f;
        for (int j = 0; j < GMAX; ++j) {
            const float4 gb = s_gt[j];
            const float dx = fmaxf(fminf(rbb.z, gb.z) - fmaxf(rbb.x, gb.x), 0.f);
            const float dy = fmaxf(fminf(rbb.w, gb.w) - fmaxf(rbb.y, gb.y), 0.f);
            const float inter = dx * dy;
            const float sum   = arr + s_ag[j];
            hP = hP || (inter > SPOS * sum);
            aN = aN && (inter < SNEG * sum);
            if (j == g) { inter_g = inter; pos_g = SPOS * sum; }
        }

        if (owner) {
            if (!hP) {                           // row becomes pos via scatter
                atomicAdd(&f_padd, 1);
                atomicAdd(&f_psadd, scores[rr]);
            }
            if (aN) atomicAdd(&f_nsub, 1);       // was counted neg in main pass
        }

        // scatter pair not already counted as an iou>0.8 pair
        if (!(inter_g > pos_g)) {
            const float4 ab  = anchors[rr];
            const float  aw  = ab.z - ab.x;
            const float  ah  = ab.w - ab.y;
            const float4 gb  = s_gt[g];
            const float  rcx = (rbb.x + rbb.z) * 0.5f;
            const float  rcy = (rbb.y + rbb.w) * 0.5f;
            const float  d0  = fabsf(rcx - (gb.x + gb.z) * 0.5f) / aw;
            const float  d1  = fabsf(rcy - (gb.y + gb.w) * 0.5f) / ah;
            const float  d2  = fabsf(logf(rbb.z - rbb.x) - logf(gb.z - gb.x));
            const float  d3  = fabsf(logf(rbb.w - rbb.y) - logf(gb.w - gb.y));
            atomicAdd(&f_radd, 0.25f * (sl1(d0) + sl1(d1) + sl1(d2) + sl1(d3)));
            atomicAdd(&f_cadd, 1);
        }
    }
    __syncthreads();

    if (tid == 0) {
        const int   posG = *(volatile int*)&g_posc;
        const int   negG = *(volatile int*)&g_negc;
        const int   cntG = *(volatile int*)&g_cnt;
        const float psG  = *(volatile float*)&g_psum;
        const float rsG  = *(volatile float*)&g_rsum;

        const double n_pos = (double)(posG + f_padd);
        const double n_neg = (double)(negG - f_nsub);
        const double n     = n_pos + n_neg;

        const double C1  = 0.3132616875182228;   // log1p(exp(-1))
        const double LN2 = 0.6931471805599453;

        const double fpos_sum = n_pos * (1.0 + C1) - (double)(psG + f_psadd);
        const double cls      = (fpos_sum + n_neg * LN2) / n;

        const double reg = (double)(rsG + f_radd);
        const double cnt = (double)(cntG + f_cadd);

        const double loss = cls / n + 10.0 * reg / cnt;

        out[0] = (float)loss;
        if (out_size > 1) out[1] = (float)f_best[GMAX - 1];  // max_iou_idx
    }

    // Reset globals for the next call / replay.
    __syncthreads();
    if (tid < GMAX) g_key[tid] = 0ull;
    if (tid == 0) {
        g_posc = 0; g_negc = 0; g_cnt = 0;
        g_psum = 0.f; g_rsum = 0.f;
        g_ticket = 0u;
    }
}

// ---------------------------------------------------------------------------
// Launch
// ---------------------------------------------------------------------------
extern "C" void kernel_launch(void* const* d_in, const int* in_sizes, int n_in,
                              void* d_out, int out_size)
{
    const float*  scores  = (const float*) d_in[0];
    const float4* regions = (const float4*)d_in[1];
    const float4* anchors = (const float4*)d_in[2];
    const float4* gts     = (const float4*)d_in[3];
    const int R  = in_sizes[0];
    const int NB = (R + NT - 1) / NT;

    rpn_fused<<<NB, NT>>>(scores, regions, anchors, gts, R, NB,
                          (float*)d_out, out_size);
}

// round 6
// speedup vs baseline: 1.1446x; 1.0198x over previous
#include <cuda_runtime.h>
#include <math.h>

// Problem constants
#define NT 256           // threads per block; 2 threads per region => 128 regions/block
#define GMAX 64          // number of ground-truth boxes
#define GHALF 32

// iou > 0.8  <=>  inter > (0.8/1.8)*(ar+ag)
// iou < 0.3  <=>  inter < (0.3/1.3)*(ar+ag)
#define SPOS (0.8f / 1.8f)
#define SNEG (0.3f / 1.3f)

// Global accumulators. Zero-initialized at module load; the finalize step
// (last-ticket block) re-zeroes them, so every kernel_launch / graph replay
// starts from the zeroed state.
// Key encoding: (iou_bits << 32) | (0xFFFFFFFF - r). key==0 <=> no pair with
// inter>0 anywhere => argmax index 0 (matches jnp.argmax on all-equal row).
__device__ unsigned long long g_key[GMAX];
__device__ int          g_posc;
__device__ int          g_negc;
__device__ int          g_cnt;
__device__ float        g_psum;
__device__ float        g_rsum;
__device__ unsigned int g_ticket;

__device__ __forceinline__ float sl1(float d) {
    return (d < 1.0f) ? 0.5f * d * d : d - 0.5f;
}

// ---------------------------------------------------------------------------
// Fused kernel, 2 threads per region (gt halves) for 2x warp count.
// Main loop body is the proven round-2 form. Block-end merge to global
// atomics; last-ticket block finalizes the loss in-kernel and resets globals.
// ---------------------------------------------------------------------------
__global__ __launch_bounds__(NT)
void rpn_fused(const float* __restrict__ scores,
               const float4* __restrict__ regions,
               const float4* __restrict__ anchors,
               const float4* __restrict__ gts,
               int R, int NB,
               float* __restrict__ out, int out_size)
{
    __shared__ float4 s_gt[GMAX];
    __shared__ float  s_ag[GMAX];
    __shared__ unsigned long long s_key[GMAX];
    __shared__ int   s_posc, s_negc, s_cnt;
    __shared__ float s_psum, s_rsum;
    __shared__ int   s_last;
    // finalize-only
    __shared__ int   f_best[GMAX];
    __shared__ int   f_padd, f_nsub, f_cadd;
    __shared__ float f_psadd, f_radd;

    const int tid = threadIdx.x;
    if (tid < GMAX) {
        float4 b = gts[tid];
        s_gt[tid] = b;
        s_ag[tid] = (b.z - b.x) * (b.w - b.y);
        s_key[tid] = 0ull;
    }
    if (tid == 0) { s_posc = 0; s_negc = 0; s_cnt = 0; s_psum = 0.f; s_rsum = 0.f; }
    __syncthreads();

    const int r  = blockIdx.x * (NT / 2) + (tid >> 1);
    const int g0 = (tid & 1) * GHALF;       // this thread's gt half: [g0, g0+32)

    if (r < R) {
        const float4 rb = regions[r];
        const float  ar = (rb.z - rb.x) * (rb.w - rb.y);

        bool hasPos = false;    // over this thread's half
        bool allNeg = true;

        #pragma unroll 16
        for (int gi = 0; gi < GHALF; ++gi) {
            const int g = g0 + gi;
            const float4 gb = s_gt[g];
            float dx = fminf(rb.z, gb.z) - fmaxf(rb.x, gb.x);
            float dy = fminf(rb.w, gb.w) - fmaxf(rb.y, gb.y);
            dx = fmaxf(dx, 0.0f);
            dy = fmaxf(dy, 0.0f);
            const float inter = dx * dy;
            const float sum   = ar + s_ag[g];

            hasPos = hasPos || (inter > SPOS * sum);
            allNeg = allNeg && (inter < SNEG * sum);

            // argmax filter without division: iou > cur  <=>  inter > cur*denom
            // (read only the iou high word: 32-bit volatile load)
            const float denom = sum - inter;   // always > 0
            const unsigned cur_bits =
                *((volatile unsigned*)&s_key[g] + 1);   // little-endian high word
            const float cur = __uint_as_float(cur_bits);
            if (inter > cur * denom) {
                const float iou = inter / denom;
                const unsigned long long key =
                    ((unsigned long long)__float_as_uint(iou) << 32) |
                    (unsigned long long)(0xFFFFFFFFu - (unsigned)r);
                atomicMax(&s_key[g], key);
            }
        }

        // rare regression pairs (iou > 0.8) within this thread's half
        if (hasPos) {
            const float4 ab  = anchors[r];
            const float  aw  = ab.z - ab.x;
            const float  ah  = ab.w - ab.y;
            const float  rcx = (rb.x + rb.z) * 0.5f;
            const float  rcy = (rb.y + rb.w) * 0.5f;
            const float  lrw = logf(rb.z - rb.x);
            const float  lrh = logf(rb.w - rb.y);

            float rsum = 0.0f;
            int   c    = 0;
            for (int gi = 0; gi < GHALF; ++gi) {
                const int g = g0 + gi;
                const float4 gb = s_gt[g];
                float dx = fminf(rb.z, gb.z) - fmaxf(rb.x, gb.x);
                float dy = fminf(rb.w, gb.w) - fmaxf(rb.y, gb.y);
                dx = fmaxf(dx, 0.0f);
                dy = fmaxf(dy, 0.0f);
                const float inter = dx * dy;
                const float sum   = ar + s_ag[g];
                if (inter > SPOS * sum) {
                    const float gcx = (gb.x + gb.z) * 0.5f;
                    const float gcy = (gb.y + gb.w) * 0.5f;
                    const float d0 = fabsf(rcx - gcx) / aw;
                    const float d1 = fabsf(rcy - gcy) / ah;
                    const float d2 = fabsf(lrw - logf(gb.z - gb.x));
                    const float d3 = fabsf(lrh - logf(gb.w - gb.y));
                    rsum += 0.25f * (sl1(d0) + sl1(d1) + sl1(d2) + sl1(d3));
                    ++c;
                }
            }
            if (c) { atomicAdd(&s_rsum, rsum); atomicAdd(&s_cnt, c); }
        }

        // combine halves (partner lane = lane^1) and account labels once
        const unsigned hp2 = __shfl_xor_sync(0xFFFFFFFFu, (unsigned)hasPos, 1);
        const unsigned an2 = __shfl_xor_sync(0xFFFFFFFFu, (unsigned)allNeg, 1);
        if ((tid & 1) == 0) {
            const bool hpFull = hasPos || hp2;
            const bool anFull = allNeg && an2;
            if (anFull) atomicAdd(&s_negc, 1);
            if (hpFull) {
                atomicAdd(&s_posc, 1);
                atomicAdd(&s_psum, scores[r]);
            }
        }
    } else {
        // keep the shuffles convergent for out-of-range threads
        __shfl_xor_sync(0xFFFFFFFFu, 0u, 1);
        __shfl_xor_sync(0xFFFFFFFFu, 0u, 1);
    }

    __syncthreads();
    // Block-end merge straight into global accumulators (no-return -> RED).
    if (tid < GMAX) {
        const unsigned long long k = s_key[tid];
        if (k) atomicMax(&g_key[tid], k);
    }
    if (tid == 0) {
        if (s_posc) { atomicAdd(&g_posc, s_posc); atomicAdd(&g_psum, s_psum); }
        if (s_negc)   atomicAdd(&g_negc, s_negc);
        if (s_cnt)  { atomicAdd(&g_cnt, s_cnt);   atomicAdd(&g_rsum, s_rsum); }
    }
    __threadfence();        // order this block's merges before the ticket
    __syncthreads();
    if (tid == 0) {
        s_last = (atomicAdd(&g_ticket, 1u) == (unsigned)(NB - 1));
        f_padd = 0; f_nsub = 0; f_cadd = 0; f_psadd = 0.f; f_radd = 0.f;
    }
    __syncthreads();
    if (!s_last) return;

    // ======================= FINALIZE (last block only) =====================
    __threadfence();        // acquire: all other blocks' merges are visible

    if (tid < GMAX) {
        const unsigned long long k = *(volatile unsigned long long*)&g_key[tid];
        f_best[tid] = (k == 0ull) ? 0
                    : (int)(0xFFFFFFFFu - (unsigned)(k & 0xFFFFFFFFull));
    }
    __syncthreads();

    if (tid < GMAX) {
        const int g  = tid;
        const int rr = f_best[g];

        bool owner = true;                       // first gt using this row
        for (int j = 0; j < g; ++j)
            if (f_best[j] == rr) owner = false;

        const float4 rbb = regions[rr];
        const float  arr = (rbb.z - rbb.x) * (rbb.w - rbb.y);

        bool hP = false, aN = true;
        float inter_g = 0.f, pos_g = 0.f;
        for (int j = 0; j < GMAX; ++j) {
            const float4 gb = s_gt[j];
            const float dx = fmaxf(fminf(rbb.z, gb.z) - fmaxf(rbb.x, gb.x), 0.f);
            const float dy = fmaxf(fminf(rbb.w, gb.w) - fmaxf(rbb.y, gb.y), 0.f);
            const float inter = dx * dy;
            const float sum   = arr + s_ag[j];
            hP = hP || (inter > SPOS * sum);
            aN = aN && (inter < SNEG * sum);
            if (j == g) { inter_g = inter; pos_g = SPOS * sum; }
        }

        if (owner) {
            if (!hP) {                           // row becomes pos via scatter
                atomicAdd(&f_padd, 1);
                atomicAdd(&f_psadd, scores[rr]);
            }
            if (aN) atomicAdd(&f_nsub, 1);       // was counted neg in main pass
        }

        // scatter pair not already counted as an iou>0.8 pair
        if (!(inter_g > pos_g)) {
            const float4 ab  = anchors[rr];
            const float  aw  = ab.z - ab.x;
            const float  ah  = ab.w - ab.y;
            const float4 gb  = s_gt[g];
            const float  rcx = (rbb.x + rbb.z) * 0.5f;
            const float  rcy = (rbb.y + rbb.w) * 0.5f;
            const float  d0  = fabsf(rcx - (gb.x + gb.z) * 0.5f) / aw;
            const float  d1  = fabsf(rcy - (gb.y + gb.w) * 0.5f) / ah;
            const float  d2  = fabsf(logf(rbb.z - rbb.x) - logf(gb.z - gb.x));
            const float  d3  = fabsf(logf(rbb.w - rbb.y) - logf(gb.w - gb.y));
            atomicAdd(&f_radd, 0.25f * (sl1(d0) + sl1(d1) + sl1(d2) + sl1(d3)));
            atomicAdd(&f_cadd, 1);
        }
    }
    __syncthreads();

    if (tid == 0) {
        const int   posG = *(volatile int*)&g_posc;
        const int   negG = *(volatile int*)&g_negc;
        const int   cntG = *(volatile int*)&g_cnt;
        const float psG  = *(volatile float*)&g_psum;
        const float rsG  = *(volatile float*)&g_rsum;

        const double n_pos = (double)(posG + f_padd);
        const double n_neg = (double)(negG - f_nsub);
        const double n     = n_pos + n_neg;

        const double C1  = 0.3132616875182228;   // log1p(exp(-1))
        const double LN2 = 0.6931471805599453;

        const double fpos_sum = n_pos * (1.0 + C1) - (double)(psG + f_psadd);
        const double cls      = (fpos_sum + n_neg * LN2) / n;

        const double reg = (double)(rsG + f_radd);
        const double cnt = (double)(cntG + f_cadd);

        const double loss = cls / n + 10.0 * reg / cnt;

        out[0] = (float)loss;
        if (out_size > 1) out[1] = (float)f_best[GMAX - 1];  // max_iou_idx
    }

    // Reset globals for the next call / replay.
    __syncthreads();
    if (tid < GMAX) g_key[tid] = 0ull;
    if (tid == 0) {
        g_posc = 0; g_negc = 0; g_cnt = 0;
        g_psum = 0.f; g_rsum = 0.f;
        g_ticket = 0u;
    }
}

// ---------------------------------------------------------------------------
// Launch
// ---------------------------------------------------------------------------
extern "C" void kernel_launch(void* const* d_in, const int* in_sizes, int n_in,
                              void* d_out, int out_size)
{
    const float*  scores  = (const float*) d_in[0];
    const float4* regions = (const float4*)d_in[1];
    const float4* anchors = (const float4*)d_in[2];
    const float4* gts     = (const float4*)d_in[3];
    const int R  = in_sizes[0];
    const int NB = (R + (NT / 2) - 1) / (NT / 2);   // 128 regions per block

    rpn_fused<<<NB, NT>>>(scores, regions, anchors, gts, R, NB,
                          (float*)d_out, out_size);
}